// round 1
// baseline (speedup 1.0000x reference)
#include <cuda_runtime.h>
#include <cstdint>

// ---------------------------------------------------------------------------
// CPC_80736795230858 : GRU(8192x256, hid 256) + CPC NCE scoring
// Inputs : data[1,8192,256] f32, Wih[768,256], Whh[768,256], bih[768], bhh[768]
// Output : z (8192*256 f32) ++ nce (1) ++ acc (1)
// ---------------------------------------------------------------------------

#define SEQ      8192
#define DIMF     256
#define HID3     768
#define NEG_DIST 1365          // 8192 // 6
#define T_START  1024          // 8192 // 8  (< end)
#define T_CNT    5791          // end(6815) - start(1024)
#define Z_ELEMS  (SEQ * DIMF)

typedef unsigned long long ull;

// -------- scratch (device globals; no allocation allowed) ------------------
__device__ float g_xw[SEQ * HID3];     // precomputed x @ Wih^T + bih  (24 MB)
__device__ float g_dnorm[SEQ];         // row norms of data
__device__ float g_pnce[T_CNT];        // per-t partial sum of logp0
__device__ float g_pcorr[T_CNT];       // per-t correct count

// -------- small helpers ----------------------------------------------------
__device__ __forceinline__ void fma2(ull &acc, ull a, ull b) {
    asm("fma.rn.f32x2 %0, %1, %2, %0;" : "+l"(acc) : "l"(a), "l"(b));
}
__device__ __forceinline__ float psum2(ull a) {
    float lo, hi;
    asm("mov.b64 {%0,%1}, %2;" : "=f"(lo), "=f"(hi) : "l"(a));
    return lo + hi;
}
__device__ __forceinline__ float sigm_f(float x) {
    return 1.0f / (1.0f + __expf(-x));
}
__device__ __forceinline__ float tanh_f(float x) {
    return 1.0f - 2.0f / (__expf(2.0f * x) + 1.0f);
}
__device__ __forceinline__ uint32_t mapa_u32(uint32_t addr, uint32_t rank) {
    uint32_t d;
    asm("mapa.shared::cluster.u32 %0, %1, %2;" : "=r"(d) : "r"(addr), "r"(rank));
    return d;
}

// ---------------------------------------------------------------------------
// Kernel 1: xW = data @ Wih^T + bih   (M=8192, N=768, K=256)
// ---------------------------------------------------------------------------
__global__ __launch_bounds__(256) void cpc_xw_gemm(
    const float* __restrict__ A,    // data [8192,256]
    const float* __restrict__ B,    // Wih  [768,256]
    const float* __restrict__ bias) // bih  [768]
{
    __shared__ float sA[16][65];
    __shared__ float sB[16][65];
    const int bx = blockIdx.x;           // N tile (12)
    const int by = blockIdx.y;           // M tile (128)
    const int tid = threadIdx.x;
    const int tx = tid & 15, ty = tid >> 4;

    float acc[4][4];
#pragma unroll
    for (int i = 0; i < 4; i++)
#pragma unroll
        for (int j = 0; j < 4; j++) acc[i][j] = 0.0f;

    const int lrow = tid >> 2;           // 0..63
    const int lkc  = (tid & 3) * 4;      // 0,4,8,12

    for (int k0 = 0; k0 < DIMF; k0 += 16) {
        float4 va = *(const float4*)(A + (by * 64 + lrow) * DIMF + k0 + lkc);
        float4 vb = *(const float4*)(B + (bx * 64 + lrow) * DIMF + k0 + lkc);
        sA[lkc + 0][lrow] = va.x; sA[lkc + 1][lrow] = va.y;
        sA[lkc + 2][lrow] = va.z; sA[lkc + 3][lrow] = va.w;
        sB[lkc + 0][lrow] = vb.x; sB[lkc + 1][lrow] = vb.y;
        sB[lkc + 2][lrow] = vb.z; sB[lkc + 3][lrow] = vb.w;
        __syncthreads();
#pragma unroll
        for (int kk = 0; kk < 16; kk++) {
            float a[4], b[4];
#pragma unroll
            for (int i = 0; i < 4; i++) a[i] = sA[kk][ty * 4 + i];
#pragma unroll
            for (int j = 0; j < 4; j++) b[j] = sB[kk][tx * 4 + j];
#pragma unroll
            for (int i = 0; i < 4; i++)
#pragma unroll
                for (int j = 0; j < 4; j++) acc[i][j] += a[i] * b[j];
        }
        __syncthreads();
    }
#pragma unroll
    for (int i = 0; i < 4; i++) {
        int m = by * 64 + ty * 4 + i;
#pragma unroll
        for (int j = 0; j < 4; j++) {
            int n = bx * 64 + tx * 4 + j;
            g_xw[m * HID3 + n] = acc[i][j] + bias[n];
        }
    }
}

// ---------------------------------------------------------------------------
// Kernel 2: row norms of data (one warp per row)
// ---------------------------------------------------------------------------
__global__ __launch_bounds__(256) void cpc_norms(const float* __restrict__ data)
{
    int row = blockIdx.x * 8 + (threadIdx.x >> 5);
    int l = threadIdx.x & 31;
    const float4* p = (const float4*)(data + row * DIMF);
    float s = 0.0f;
#pragma unroll
    for (int i = l; i < 64; i += 32) {
        float4 v = p[i];
        s += v.x * v.x + v.y * v.y + v.z * v.z + v.w * v.w;
    }
#pragma unroll
    for (int off = 16; off > 0; off >>= 1)
        s += __shfl_xor_sync(0xffffffffu, s, off);
    if (l == 0) g_dnorm[row] = fmaxf(sqrtf(s), 1e-8f);
}

// ---------------------------------------------------------------------------
// Kernel 3: GRU recurrence — 8-CTA cluster, Whh register-resident.
// CTA c owns hidden indices [32c, 32c+32) and their r/z/n gate rows.
// ---------------------------------------------------------------------------
__global__ void __cluster_dims__(8, 1, 1) __launch_bounds__(256, 1)
cpc_gru(const float* __restrict__ Whh,
        const float* __restrict__ bhh,
        float* __restrict__ z)
{
    __shared__ float hbuf[2][256];        // double-buffered hidden state
    __shared__ float part[3][8][32];      // matvec partials [gate][kchunk][lane]

    const int tid = threadIdx.x;
    const int w = tid >> 5, l = tid & 31;
    uint32_t rank;
    asm("mov.u32 %0, %%cluster_ctarank;" : "=r"(rank));
    const int j = (int)rank * 32 + l;     // global hidden index this lane owns

    // ---- load this thread's Whh slice into registers as f32x2 pairs ----
    // rows: r=j, z=256+j, n=512+j ; k in [32w, 32w+32)
    ull wr[16], wz[16], wn[16];
    {
        const ull* pr = (const ull*)(Whh + (j      ) * DIMF + 32 * w);
        const ull* pz = (const ull*)(Whh + (256 + j) * DIMF + 32 * w);
        const ull* pn = (const ull*)(Whh + (512 + j) * DIMF + 32 * w);
#pragma unroll
        for (int i = 0; i < 16; i++) { wr[i] = pr[i]; wz[i] = pz[i]; wn[i] = pn[i]; }
    }

    float bh_r = 0, bh_z = 0, bh_n = 0, xr = 0, xz = 0, xn = 0;
    uint32_t peer[8];
    uint32_t hb = (uint32_t)__cvta_generic_to_shared(&hbuf[0][0]);
    if (w == 0) {
        bh_r = bhh[j]; bh_z = bhh[256 + j]; bh_n = bhh[512 + j];
        xr = g_xw[j];  xz = g_xw[256 + j]; xn = g_xw[512 + j];   // prefetch t=0
#pragma unroll
        for (int r = 0; r < 8; r++) peer[r] = mapa_u32(hb, (uint32_t)r);
    }
    ((float*)hbuf)[tid] = 0.0f;
    ((float*)hbuf)[tid + 256] = 0.0f;
    __syncthreads();
    asm volatile("barrier.cluster.arrive.aligned;" ::: "memory");
    asm volatile("barrier.cluster.wait.aligned;"   ::: "memory");

    for (int t = 0; t < SEQ; t++) {
        const int p = t & 1;
        // ---- matvec: gh[rows] += Whh_slice * h  (f32x2, smem broadcast) ----
        const ull* h2 = (const ull*)(&hbuf[p][32 * w]);
        ull ar = 0, az = 0, an = 0;
#pragma unroll
        for (int i = 0; i < 16; i++) {
            ull hv = h2[i];
            fma2(ar, wr[i], hv);
            fma2(az, wz[i], hv);
            fma2(an, wn[i], hv);
        }
        part[0][w][l] = psum2(ar);
        part[1][w][l] = psum2(az);
        part[2][w][l] = psum2(an);
        __syncthreads();

        if (w == 0) {
            float hr = bh_r, hz = bh_z, hn = bh_n;
#pragma unroll
            for (int q = 0; q < 8; q++) {
                hr += part[0][q][l];
                hz += part[1][q][l];
                hn += part[2][q][l];
            }
            float rg = sigm_f(xr + hr);
            float zg = sigm_f(xz + hz);
            float ng = tanh_f(xn + rg * hn);
            float hnew = (1.0f - zg) * ng + zg * hbuf[p][j];
            z[t * DIMF + j] = hnew;
            // broadcast my hidden element to all 8 CTAs' other h buffer
            uint32_t off = (uint32_t)(((p ^ 1) * 256 + j) * 4);
#pragma unroll
            for (int r = 0; r < 8; r++) {
                asm volatile("st.shared::cluster.f32 [%0], %1;"
                             :: "r"(peer[r] + off), "f"(hnew) : "memory");
            }
            if (t + 1 < SEQ) {           // prefetch next step's xW row
                const float* xwp = g_xw + (t + 1) * HID3;
                xr = xwp[j]; xz = xwp[256 + j]; xn = xwp[512 + j];
            }
        }
        asm volatile("barrier.cluster.arrive.aligned;" ::: "memory");
        asm volatile("barrier.cluster.wait.aligned;"   ::: "memory");
    }
}

// ---------------------------------------------------------------------------
// Kernel 4: CPC scoring — one block per t
// ---------------------------------------------------------------------------
__global__ __launch_bounds__(256) void cpc_score(
    const float* __restrict__ z,     // = d_out (8192x256)
    const float* __restrict__ data)
{
    const int bt = blockIdx.x;
    const int t = T_START + bt;
    __shared__ float c[256];
    __shared__ float sims[40];
    __shared__ float wsum[8];
    __shared__ float cn;
    __shared__ float resN[4], resC[4];

    const int tid = threadIdx.x;
    const int w = tid >> 5, l = tid & 31;

    float v = z[t * DIMF + tid];
    c[tid] = v;
    float s = v * v;
#pragma unroll
    for (int off = 16; off > 0; off >>= 1)
        s += __shfl_xor_sync(0xffffffffu, s, off);
    if (l == 0) wsum[w] = s;
    __syncthreads();
    if (tid == 0) {
        float tot = 0;
#pragma unroll
        for (int q = 0; q < 8; q++) tot += wsum[q];
        cn = fmaxf(sqrtf(tot), 1e-8f);
    }
    __syncthreads();

    // 40 cosine sims: warp w does ids w*5 .. w*5+4
#pragma unroll
    for (int d = 0; d < 5; d++) {
        int id = w * 5 + d;
        int sp = id / 10 + 1;            // 1..4
        int n = id % 10;                 // 0 = positive
        int row = t + sp + (n ? (NEG_DIST + n - 1) : 0);
        const float* x = data + row * DIMF;
        float dot = 0.0f;
#pragma unroll
        for (int i = 0; i < 8; i++) dot += x[l + 32 * i] * c[l + 32 * i];
#pragma unroll
        for (int off = 16; off > 0; off >>= 1)
            dot += __shfl_xor_sync(0xffffffffu, dot, off);
        if (l == 0) sims[id] = dot / (g_dnorm[row] * cn);
    }
    __syncthreads();

    if (tid < 4) {
        const float* sm = sims + tid * 10;
        float s0 = sm[0];
        float mx = sm[1];
#pragma unroll
        for (int n = 2; n < 10; n++) mx = fmaxf(mx, sm[n]);
        float M = fmaxf(mx, s0);
        float se = 0.0f;
#pragma unroll
        for (int n = 0; n < 10; n++) se += __expf(sm[n] - M);
        resN[tid] = s0 - (M + __logf(se));
        resC[tid] = (s0 >= mx) ? 1.0f : 0.0f;
    }
    __syncthreads();
    if (tid == 0) {
        g_pnce[bt]  = resN[0] + resN[1] + resN[2] + resN[3];
        g_pcorr[bt] = resC[0] + resC[1] + resC[2] + resC[3];
    }
}

// ---------------------------------------------------------------------------
// Kernel 5: final deterministic reduction -> nce, acc
// ---------------------------------------------------------------------------
__global__ __launch_bounds__(256) void cpc_final(float* __restrict__ out)
{
    __shared__ double sN[256], sC[256];
    const int tid = threadIdx.x;
    double a = 0.0, b = 0.0;
    for (int i = tid; i < T_CNT; i += 256) { a += (double)g_pnce[i]; b += (double)g_pcorr[i]; }
    sN[tid] = a; sC[tid] = b;
    __syncthreads();
    for (int s = 128; s > 0; s >>= 1) {
        if (tid < s) { sN[tid] += sN[tid + s]; sC[tid] += sC[tid + s]; }
        __syncthreads();
    }
    if (tid == 0) {
        const double denom = (double)T_CNT * 4.0;   // 23164
        out[Z_ELEMS]     = (float)(-sN[0] / denom);
        out[Z_ELEMS + 1] = (float)( sC[0] / denom);
    }
}

// ---------------------------------------------------------------------------
extern "C" void kernel_launch(void* const* d_in, const int* in_sizes, int n_in,
                              void* d_out, int out_size)
{
    const float* data = (const float*)d_in[0];
    const float* Wih  = (const float*)d_in[1];
    const float* Whh  = (const float*)d_in[2];
    const float* bih  = (const float*)d_in[3];
    const float* bhh  = (const float*)d_in[4];
    float* out = (float*)d_out;

    dim3 gg(12, 128);
    cpc_xw_gemm<<<gg, 256>>>(data, Wih, bih);
    cpc_norms<<<SEQ / 8, 256>>>(data);
    cpc_gru<<<8, 256>>>(Whh, bhh, out);
    cpc_score<<<T_CNT, 256>>>(out, data);
    cpc_final<<<1, 256>>>(out);
}

// round 2
// speedup vs baseline: 1.3443x; 1.3443x over previous
#include <cuda_runtime.h>
#include <cstdint>

// ---------------------------------------------------------------------------
// CPC_80736795230858 : GRU(8192x256, hid 256) + CPC NCE scoring
// Inputs : data[1,8192,256] f32, Wih[768,256], Whh[768,256], bih[768], bhh[768]
// Output : z (8192*256 f32) ++ nce (1) ++ acc (1)
// ---------------------------------------------------------------------------

#define SEQ      8192
#define DIMF     256
#define HID3     768
#define NEG_DIST 1365          // 8192 // 6
#define T_START  1024          // 8192 // 8  (< end)
#define T_CNT    5791          // end(6815) - start(1024)
#define Z_ELEMS  (SEQ * DIMF)

typedef unsigned long long ull;

// -------- scratch (device globals; no allocation allowed) ------------------
__device__ float g_xw[SEQ * HID3];     // precomputed x @ Wih^T + bih  (24 MB)
__device__ float g_dnorm[SEQ];         // row norms of data
__device__ float g_pnce[T_CNT];        // per-t partial sum of logp0
__device__ float g_pcorr[T_CNT];       // per-t correct count

// -------- small helpers ----------------------------------------------------
__device__ __forceinline__ void fma2(ull &acc, ull a, ull b) {
    asm("fma.rn.f32x2 %0, %1, %2, %0;" : "+l"(acc) : "l"(a), "l"(b));
}
__device__ __forceinline__ float psum2(ull a) {
    float lo, hi;
    asm("mov.b64 {%0,%1}, %2;" : "=f"(lo), "=f"(hi) : "l"(a));
    return lo + hi;
}
__device__ __forceinline__ float sigm_f(float x) {
    return 1.0f / (1.0f + __expf(-x));
}
__device__ __forceinline__ float tanh_f(float x) {
    return 1.0f - 2.0f / (__expf(2.0f * x) + 1.0f);
}
__device__ __forceinline__ uint32_t mapa_u32(uint32_t addr, uint32_t rank) {
    uint32_t d;
    asm("mapa.shared::cluster.u32 %0, %1, %2;" : "=r"(d) : "r"(addr), "r"(rank));
    return d;
}
__device__ __forceinline__ void mbar_init(uint32_t mbar, uint32_t cnt) {
    asm volatile("mbarrier.init.shared.b64 [%0], %1;" :: "r"(mbar), "r"(cnt) : "memory");
}
__device__ __forceinline__ void mbar_arrive_expect_tx(uint32_t mbar, uint32_t bytes) {
    asm volatile("mbarrier.arrive.expect_tx.shared::cta.b64 _, [%0], %1;"
                 :: "r"(mbar), "r"(bytes) : "memory");
}
__device__ __forceinline__ void st_async_f32(uint32_t raddr, float v, uint32_t rmbar) {
    asm volatile("st.async.shared::cluster.mbarrier::complete_tx::bytes.f32 [%0], %1, [%2];"
                 :: "r"(raddr), "f"(v), "r"(rmbar) : "memory");
}
__device__ __forceinline__ void wait_parity_cluster(uint32_t mbar, uint32_t parity) {
    asm volatile(
        "{\n\t"
        ".reg .pred P;\n\t"
        "WL%=:\n\t"
        "mbarrier.try_wait.parity.acquire.cluster.shared::cta.b64 P, [%0], %1, 0x989680;\n\t"
        "@P bra.uni WD%=;\n\t"
        "bra.uni WL%=;\n\t"
        "WD%=:\n\t"
        "}"
        :: "r"(mbar), "r"(parity) : "memory");
}

// ---------------------------------------------------------------------------
// Kernel 1: xW = data @ Wih^T + bih   (M=8192, N=768, K=256)
// ---------------------------------------------------------------------------
__global__ __launch_bounds__(256) void cpc_xw_gemm(
    const float* __restrict__ A,    // data [8192,256]
    const float* __restrict__ B,    // Wih  [768,256]
    const float* __restrict__ bias) // bih  [768]
{
    __shared__ float sA[16][65];
    __shared__ float sB[16][65];
    const int bx = blockIdx.x;           // N tile (12)
    const int by = blockIdx.y;           // M tile (128)
    const int tid = threadIdx.x;
    const int tx = tid & 15, ty = tid >> 4;

    float acc[4][4];
#pragma unroll
    for (int i = 0; i < 4; i++)
#pragma unroll
        for (int j = 0; j < 4; j++) acc[i][j] = 0.0f;

    const int lrow = tid >> 2;           // 0..63
    const int lkc  = (tid & 3) * 4;      // 0,4,8,12

    for (int k0 = 0; k0 < DIMF; k0 += 16) {
        float4 va = *(const float4*)(A + (by * 64 + lrow) * DIMF + k0 + lkc);
        float4 vb = *(const float4*)(B + (bx * 64 + lrow) * DIMF + k0 + lkc);
        sA[lkc + 0][lrow] = va.x; sA[lkc + 1][lrow] = va.y;
        sA[lkc + 2][lrow] = va.z; sA[lkc + 3][lrow] = va.w;
        sB[lkc + 0][lrow] = vb.x; sB[lkc + 1][lrow] = vb.y;
        sB[lkc + 2][lrow] = vb.z; sB[lkc + 3][lrow] = vb.w;
        __syncthreads();
#pragma unroll
        for (int kk = 0; kk < 16; kk++) {
            float a[4], b[4];
#pragma unroll
            for (int i = 0; i < 4; i++) a[i] = sA[kk][ty * 4 + i];
#pragma unroll
            for (int j = 0; j < 4; j++) b[j] = sB[kk][tx * 4 + j];
#pragma unroll
            for (int i = 0; i < 4; i++)
#pragma unroll
                for (int j = 0; j < 4; j++) acc[i][j] += a[i] * b[j];
        }
        __syncthreads();
    }
#pragma unroll
    for (int i = 0; i < 4; i++) {
        int m = by * 64 + ty * 4 + i;
#pragma unroll
        for (int j = 0; j < 4; j++) {
            int n = bx * 64 + tx * 4 + j;
            g_xw[m * HID3 + n] = acc[i][j] + bias[n];
        }
    }
}

// ---------------------------------------------------------------------------
// Kernel 2: row norms of data (one warp per row)
// ---------------------------------------------------------------------------
__global__ __launch_bounds__(256) void cpc_norms(const float* __restrict__ data)
{
    int row = blockIdx.x * 8 + (threadIdx.x >> 5);
    int l = threadIdx.x & 31;
    const float4* p = (const float4*)(data + row * DIMF);
    float s = 0.0f;
#pragma unroll
    for (int i = l; i < 64; i += 32) {
        float4 v = p[i];
        s += v.x * v.x + v.y * v.y + v.z * v.z + v.w * v.w;
    }
#pragma unroll
    for (int off = 16; off > 0; off >>= 1)
        s += __shfl_xor_sync(0xffffffffu, s, off);
    if (l == 0) g_dnorm[row] = fmaxf(sqrtf(s), 1e-8f);
}

// ---------------------------------------------------------------------------
// Kernel 3: GRU recurrence — 8-CTA cluster, Whh register-resident.
// CTA c owns hidden indices [32c, 32c+32) and their r/z/n gate rows.
// Cross-CTA h broadcast via st.async + mbarrier tx-count (no barrier.cluster
// in the steady state).
// ---------------------------------------------------------------------------
__global__ void __cluster_dims__(8, 1, 1) __launch_bounds__(256, 1)
cpc_gru(const float* __restrict__ Whh,
        const float* __restrict__ bhh,
        float* __restrict__ z)
{
    __shared__ float hbuf[2][256];             // double-buffered hidden state
    __shared__ float part[3][8][32];           // matvec partials [gate][kchunk][lane]
    __shared__ alignas(16) ull mbar[2];        // one mbarrier per h buffer

    const int tid = threadIdx.x;
    const int w = tid >> 5, l = tid & 31;
    uint32_t rank;
    asm("mov.u32 %0, %%cluster_ctarank;" : "=r"(rank));
    const int j = (int)rank * 32 + l;          // hidden index this lane owns

    // ---- load this thread's Whh slice into registers as f32x2 pairs ----
    ull wr[16], wz[16], wn[16];
    {
        const ull* pr = (const ull*)(Whh + (j      ) * DIMF + 32 * w);
        const ull* pz = (const ull*)(Whh + (256 + j) * DIMF + 32 * w);
        const ull* pn = (const ull*)(Whh + (512 + j) * DIMF + 32 * w);
#pragma unroll
        for (int i = 0; i < 16; i++) { wr[i] = pr[i]; wz[i] = pz[i]; wn[i] = pn[i]; }
    }

    const uint32_t hb = (uint32_t)__cvta_generic_to_shared(&hbuf[0][0]);
    const uint32_t mb = (uint32_t)__cvta_generic_to_shared(&mbar[0]);

    float bh_r = 0, bh_z = 0, bh_n = 0, xr = 0, xz = 0, xn = 0;
    uint32_t peer_h[8], peer_m[8];
    if (w == 0) {
        bh_r = bhh[j]; bh_z = bhh[256 + j]; bh_n = bhh[512 + j];
        xr = g_xw[j];  xz = g_xw[256 + j]; xn = g_xw[512 + j];   // prefetch t=0
#pragma unroll
        for (int r = 0; r < 8; r++) {
            peer_h[r] = mapa_u32(hb, (uint32_t)r);
            peer_m[r] = mapa_u32(mb, (uint32_t)r);
        }
    }
    if (tid == 0) { mbar_init(mb, 1); mbar_init(mb + 8, 1); }
    ((float*)hbuf)[tid] = 0.0f;
    ((float*)hbuf)[tid + 256] = 0.0f;
    __syncthreads();
    // one-time cluster barrier: all mbarriers initialized, h zeroed
    asm volatile("barrier.cluster.arrive.aligned;" ::: "memory");
    asm volatile("barrier.cluster.wait.aligned;"   ::: "memory");

    uint32_t ph[2] = {0u, 0u};                 // wait parity per buffer

    for (int t = 0; t < SEQ; t++) {
        const int p = t & 1;
        const int q = p ^ 1;

        // ---- matvec: gh[rows] += Whh_slice * h  (f32x2, smem broadcast) ----
        const ull* h2 = (const ull*)(&hbuf[p][32 * w]);
        ull ar = 0, az = 0, an = 0;
#pragma unroll
        for (int i = 0; i < 16; i++) {
            ull hv = h2[i];
            fma2(ar, wr[i], hv);
            fma2(az, wz[i], hv);
            fma2(an, wn[i], hv);
        }
        part[0][w][l] = psum2(ar);
        part[1][w][l] = psum2(az);
        part[2][w][l] = psum2(an);
        if (tid == 0) mbar_arrive_expect_tx(mb + q * 8, 1024u);
        __syncthreads();

        if (w == 0) {
            // prefetch next step's xW row early (latency covered by the wait)
            float nxr = 0, nxz = 0, nxn = 0;
            if (t + 1 < SEQ) {
                const float* xwp = g_xw + (t + 1) * HID3;
                nxr = xwp[j]; nxz = xwp[256 + j]; nxn = xwp[512 + j];
            }
            // conflict-free reduce: part[g][qk][l] over 8 k-chunks, tree sums
            float hr = ((part[0][0][l] + part[0][1][l]) + (part[0][2][l] + part[0][3][l]))
                     + ((part[0][4][l] + part[0][5][l]) + (part[0][6][l] + part[0][7][l]));
            float hz = ((part[1][0][l] + part[1][1][l]) + (part[1][2][l] + part[1][3][l]))
                     + ((part[1][4][l] + part[1][5][l]) + (part[1][6][l] + part[1][7][l]));
            float hn = ((part[2][0][l] + part[2][1][l]) + (part[2][2][l] + part[2][3][l]))
                     + ((part[2][4][l] + part[2][5][l]) + (part[2][6][l] + part[2][7][l]));
            float rg = sigm_f(xr + (bh_r + hr));
            float zg = sigm_f(xz + (bh_z + hz));
            float ng = tanh_f(xn + rg * (bh_n + hn));
            float hold = hbuf[p][j];
            float hnew = ng + zg * (hold - ng);
            // broadcast my hidden element to all 8 CTAs' other h buffer
            const uint32_t off = (uint32_t)((q * 256 + j) * 4);
            const uint32_t mof = (uint32_t)(q * 8);
#pragma unroll
            for (int r = 0; r < 8; r++)
                st_async_f32(peer_h[r] + off, hnew, peer_m[r] + mof);
            z[t * DIMF + j] = hnew;
            xr = nxr; xz = nxz; xn = nxn;
        }
        // wait until all 8 CTAs' 32 floats have landed in hbuf[q]
        wait_parity_cluster(mb + q * 8, ph[q]);
        ph[q] ^= 1u;
    }
}

// ---------------------------------------------------------------------------
// Kernel 4: CPC scoring — one block per t
// ---------------------------------------------------------------------------
__global__ __launch_bounds__(256) void cpc_score(
    const float* __restrict__ z,     // = d_out (8192x256)
    const float* __restrict__ data)
{
    const int bt = blockIdx.x;
    const int t = T_START + bt;
    __shared__ float c[256];
    __shared__ float sims[40];
    __shared__ float wsum[8];
    __shared__ float cn;
    __shared__ float resN[4], resC[4];

    const int tid = threadIdx.x;
    const int w = tid >> 5, l = tid & 31;

    float v = z[t * DIMF + tid];
    c[tid] = v;
    float s = v * v;
#pragma unroll
    for (int off = 16; off > 0; off >>= 1)
        s += __shfl_xor_sync(0xffffffffu, s, off);
    if (l == 0) wsum[w] = s;
    __syncthreads();
    if (tid == 0) {
        float tot = 0;
#pragma unroll
        for (int qq = 0; qq < 8; qq++) tot += wsum[qq];
        cn = fmaxf(sqrtf(tot), 1e-8f);
    }
    __syncthreads();

    // 40 cosine sims: warp w does ids w*5 .. w*5+4
#pragma unroll
    for (int d = 0; d < 5; d++) {
        int id = w * 5 + d;
        int sp = id / 10 + 1;            // 1..4
        int n = id % 10;                 // 0 = positive
        int row = t + sp + (n ? (NEG_DIST + n - 1) : 0);
        const float* x = data + row * DIMF;
        float dot = 0.0f;
#pragma unroll
        for (int i = 0; i < 8; i++) dot += x[l + 32 * i] * c[l + 32 * i];
#pragma unroll
        for (int off = 16; off > 0; off >>= 1)
            dot += __shfl_xor_sync(0xffffffffu, dot, off);
        if (l == 0) sims[id] = dot / (g_dnorm[row] * cn);
    }
    __syncthreads();

    if (tid < 4) {
        const float* sm = sims + tid * 10;
        float s0 = sm[0];
        float mx = sm[1];
#pragma unroll
        for (int n = 2; n < 10; n++) mx = fmaxf(mx, sm[n]);
        float M = fmaxf(mx, s0);
        float se = 0.0f;
#pragma unroll
        for (int n = 0; n < 10; n++) se += __expf(sm[n] - M);
        resN[tid] = s0 - (M + __logf(se));
        resC[tid] = (s0 >= mx) ? 1.0f : 0.0f;
    }
    __syncthreads();
    if (tid == 0) {
        g_pnce[bt]  = resN[0] + resN[1] + resN[2] + resN[3];
        g_pcorr[bt] = resC[0] + resC[1] + resC[2] + resC[3];
    }
}

// ---------------------------------------------------------------------------
// Kernel 5: final deterministic reduction -> nce, acc
// ---------------------------------------------------------------------------
__global__ __launch_bounds__(256) void cpc_final(float* __restrict__ out)
{
    __shared__ double sN[256], sC[256];
    const int tid = threadIdx.x;
    double a = 0.0, b = 0.0;
    for (int i = tid; i < T_CNT; i += 256) { a += (double)g_pnce[i]; b += (double)g_pcorr[i]; }
    sN[tid] = a; sC[tid] = b;
    __syncthreads();
    for (int s = 128; s > 0; s >>= 1) {
        if (tid < s) { sN[tid] += sN[tid + s]; sC[tid] += sC[tid + s]; }
        __syncthreads();
    }
    if (tid == 0) {
        const double denom = (double)T_CNT * 4.0;   // 23164
        out[Z_ELEMS]     = (float)(-sN[0] / denom);
        out[Z_ELEMS + 1] = (float)( sC[0] / denom);
    }
}

// ---------------------------------------------------------------------------
extern "C" void kernel_launch(void* const* d_in, const int* in_sizes, int n_in,
                              void* d_out, int out_size)
{
    const float* data = (const float*)d_in[0];
    const float* Wih  = (const float*)d_in[1];
    const float* Whh  = (const float*)d_in[2];
    const float* bih  = (const float*)d_in[3];
    const float* bhh  = (const float*)d_in[4];
    float* out = (float*)d_out;

    dim3 gg(12, 128);
    cpc_xw_gemm<<<gg, 256>>>(data, Wih, bih);
    cpc_norms<<<SEQ / 8, 256>>>(data);
    cpc_gru<<<8, 256>>>(Whh, bhh, out);
    cpc_score<<<T_CNT, 256>>>(out, data);
    cpc_final<<<1, 256>>>(out);
}